// round 2
// baseline (speedup 1.0000x reference)
#include <cuda_runtime.h>
#include <cstdint>
#include <cstddef>

#define Tn 200
#define Dn 128
#define Hn 16
#define NEGV (-4294967295.0f)
#define NTHREADS 256

// smem float counts
#define SMEM_FLOATS (Tn*Dn + Dn*Hn + Dn + Hn + Hn + Tn + 16 + Dn + NTHREADS)

__global__ void __launch_bounds__(NTHREADS, 2) din_kernel(
    const float* __restrict__ query,
    const float* __restrict__ facts,
    const int* __restrict__ mask,
    const float* __restrict__ W1,
    const float* __restrict__ b1,
    const float* __restrict__ W2,
    const float* __restrict__ b2,
    float* __restrict__ out)
{
    extern __shared__ float smem[];
    float* sf     = smem;                 // Tn*Dn swizzled facts tile (100 KB)
    float* sM     = sf + Tn*Dn;           // Dn*Hn folded first-layer weights
    float* sq     = sM + Dn*Hn;           // Dn
    float* sc     = sq + Dn;              // Hn per-b bias (q-dependent + b1)
    float* sw2    = sc + Hn;              // Hn
    float* sscore = sw2 + Hn;             // Tn scores -> unnormalized attn
    float* sred   = sscore + Tn;          // 16 reduction scratch
    float* spart  = sred + 16;            // Dn weighted-sum partials
    float* scpart = spart + Dn;           // NTHREADS c-bias partials

    const int b   = blockIdx.x;
    const int tid = threadIdx.x;

    // ---- async load facts[b] into swizzled smem (16B cp.async) ----
    {
        const float4* fg = (const float4*)(facts + (size_t)b * (Tn * Dn));
        #pragma unroll
        for (int k = 0; k < (Tn * Dn / 4) / NTHREADS; ++k) {   // 25 iters
            int i  = tid + k * NTHREADS;
            int t  = i >> 5;        // 32 float4 groups per row
            int dg = i & 31;
            float4* dst = ((float4*)sf) + (t * 32 + (dg ^ (t & 31)));
            unsigned saddr = (unsigned)__cvta_generic_to_shared(dst);
            asm volatile("cp.async.cg.shared.global [%0], [%1], 16;\n"
                         :: "r"(saddr), "l"(fg + i) : "memory");
        }
        asm volatile("cp.async.commit_group;\n" ::: "memory");
    }

    if (tid < Dn) sq[tid]  = query[(size_t)b * Dn + tid];
    if (tid < Hn) sw2[tid] = W2[tid];
    __syncthreads();   // sq visible

    // ---- M[d][h] = (W1f - W1d)[d][h] + q[d] * W1m[d][h] ----
    #pragma unroll
    for (int k = 0; k < (Dn * Hn) / NTHREADS; ++k) {   // 8 iters
        int i = tid + k * NTHREADS;
        int d = i >> 4;
        int h = i & 15;
        float wf = W1[(128 + d) * Hn + h];
        float wd = W1[(256 + d) * Hn + h];
        float wm = W1[(384 + d) * Hn + h];
        sM[i] = (wf - wd) + sq[d] * wm;
    }

    // ---- c[h] = b1[h] + sum_d q[d]*(W1q + W1d)[d][h], parallel partials ----
    {
        int h     = tid & 15;
        int chunk = tid >> 4;   // 16 chunks x 8 d
        float acc = 0.f;
        #pragma unroll
        for (int j = 0; j < 8; ++j) {
            int d = chunk * 8 + j;
            acc += sq[d] * (W1[d * Hn + h] + W1[(256 + d) * Hn + h]);
        }
        scpart[tid] = acc;
    }
    __syncthreads();
    if (tid < Hn) {
        float acc = b1[tid];
        #pragma unroll
        for (int k = 0; k < 16; ++k) acc += scpart[k * 16 + tid];
        sc[tid] = acc;
    }
    asm volatile("cp.async.wait_group 0;\n" ::: "memory");
    __syncthreads();   // facts tile + sc ready

    // ---- scores: one thread per t ----
    if (tid < Tn) {
        const int t  = tid;
        const int sw = t & 31;
        const float4* frow = ((const float4*)sf) + t * 32;
        const float4* Mr   = (const float4*)sM;
        float acc[Hn];
        #pragma unroll
        for (int h = 0; h < Hn; ++h) acc[h] = 0.f;

        #pragma unroll 4
        for (int d4 = 0; d4 < 32; ++d4) {
            float4 f4 = frow[d4 ^ sw];
            float fv[4] = {f4.x, f4.y, f4.z, f4.w};
            #pragma unroll
            for (int j = 0; j < 4; ++j) {
                int d = d4 * 4 + j;
                float4 m0 = Mr[d * 4 + 0];
                float4 m1 = Mr[d * 4 + 1];
                float4 m2 = Mr[d * 4 + 2];
                float4 m3 = Mr[d * 4 + 3];
                float f = fv[j];
                acc[0]  += f * m0.x; acc[1]  += f * m0.y; acc[2]  += f * m0.z; acc[3]  += f * m0.w;
                acc[4]  += f * m1.x; acc[5]  += f * m1.y; acc[6]  += f * m1.z; acc[7]  += f * m1.w;
                acc[8]  += f * m2.x; acc[9]  += f * m2.y; acc[10] += f * m2.z; acc[11] += f * m2.w;
                acc[12] += f * m3.x; acc[13] += f * m3.y; acc[14] += f * m3.z; acc[15] += f * m3.w;
            }
        }
        float s = b2[0];
        #pragma unroll
        for (int h = 0; h < Hn; ++h) {
            float sig = 1.0f / (1.0f + __expf(-(acc[h] + sc[h])));
            s += sig * sw2[h];
        }
        if (mask[(size_t)b * Tn + t] == 0) s = NEGV;
        sscore[t] = s;
    }
    __syncthreads();

    // ---- softmax over T ----
    float v = (tid < Tn) ? sscore[tid] : -3.4e38f;
    #pragma unroll
    for (int o = 16; o > 0; o >>= 1) v = fmaxf(v, __shfl_xor_sync(0xffffffffu, v, o));
    if ((tid & 31) == 0) sred[tid >> 5] = v;
    __syncthreads();
    if (tid == 0) {
        float m = sred[0];
        #pragma unroll
        for (int w = 1; w < 8; ++w) m = fmaxf(m, sred[w]);
        sred[8] = m;
    }
    __syncthreads();
    float mx = sred[8];
    float e = 0.f;
    if (tid < Tn) {
        e = __expf(sscore[tid] - mx);
        sscore[tid] = e;     // unnormalized attn
    }
    #pragma unroll
    for (int o = 16; o > 0; o >>= 1) e += __shfl_xor_sync(0xffffffffu, e, o);
    if ((tid & 31) == 0) sred[tid >> 5] = e;
    __syncthreads();
    if (tid == 0) {
        float ssum = 0.f;
        #pragma unroll
        for (int w = 0; w < 8; ++w) ssum += sred[w];
        sred[9] = 1.0f / ssum;
    }
    __syncthreads();
    const float inv = sred[9];

    // ---- weighted sum: out[d] = inv * sum_t attn[t] * facts[t][d] ----
    {
        int d    = tid & 127;
        int half = tid >> 7;           // t-range split across the two half-blocks
        int dg   = d >> 2, dl = d & 3;
        float acc = 0.f;
        int t0 = half * 100;
        #pragma unroll 4
        for (int tt = 0; tt < 100; ++tt) {
            int t = t0 + tt;
            float f = sf[t * Dn + (((dg ^ (t & 31)) << 2) | dl)];
            acc += sscore[t] * f;
        }
        if (half) spart[d] = acc;
        __syncthreads();
        if (tid < Dn) out[(size_t)b * Dn + tid] = (acc + spart[tid]) * inv;
    }
}

extern "C" void kernel_launch(void* const* d_in, const int* in_sizes, int n_in,
                              void* d_out, int out_size) {
    const float* query = (const float*)d_in[0];
    const float* facts = (const float*)d_in[1];
    const int*   mask  = (const int*)d_in[2];
    const float* W1    = (const float*)d_in[3];
    const float* b1    = (const float*)d_in[4];
    const float* W2    = (const float*)d_in[5];
    const float* b2    = (const float*)d_in[6];
    float*       out   = (float*)d_out;

    int B = in_sizes[0] / Dn;   // 4096
    size_t smem = SMEM_FLOATS * sizeof(float);   // ~113.6 KB
    cudaFuncSetAttribute(din_kernel, cudaFuncAttributeMaxDynamicSharedMemorySize, (int)smem);
    din_kernel<<<B, NTHREADS, smem>>>(query, facts, mask, W1, b1, W2, b2, out);
}

// round 3
// speedup vs baseline: 1.3201x; 1.3201x over previous
#include <cuda_runtime.h>
#include <cstdint>
#include <cstddef>

#define Tn 200
#define Dn 128
#define Hn 16
#define NEGV (-4294967295.0f)
#define NTHREADS 256

// smem float counts
#define SMEM_FLOATS (Tn*Dn + Dn*Hn + Dn + Hn + Hn + Tn + 16 + Dn + NTHREADS)

__device__ __forceinline__ uint32_t f2tf32(float x) {
    uint32_t u;
    asm("cvt.rna.tf32.f32 %0, %1;" : "=r"(u) : "f"(x));
    return u;
}

__device__ __forceinline__ void mma_tf32(float c[4], const uint32_t a[4],
                                         uint32_t b0, uint32_t b1) {
    asm volatile(
        "mma.sync.aligned.m16n8k8.row.col.f32.tf32.tf32.f32 "
        "{%0,%1,%2,%3}, {%4,%5,%6,%7}, {%8,%9}, {%0,%1,%2,%3};"
        : "+f"(c[0]), "+f"(c[1]), "+f"(c[2]), "+f"(c[3])
        : "r"(a[0]), "r"(a[1]), "r"(a[2]), "r"(a[3]), "r"(b0), "r"(b1));
}

__global__ void __launch_bounds__(NTHREADS, 2) din_kernel(
    const float* __restrict__ query,
    const float* __restrict__ facts,
    const int* __restrict__ mask,
    const float* __restrict__ W1,
    const float* __restrict__ b1,
    const float* __restrict__ W2,
    const float* __restrict__ b2,
    float* __restrict__ out)
{
    extern __shared__ float smem[];
    float* sf     = smem;                 // Tn*Dn swizzled facts tile (100 KB)
    float* sM     = sf + Tn*Dn;           // Dn*Hn folded first-layer weights (tf32-rounded)
    float* sq     = sM + Dn*Hn;           // Dn
    float* sc     = sq + Dn;              // Hn per-b bias (q-dependent + b1)
    float* sw2    = sc + Hn;              // Hn
    float* sscore = sw2 + Hn;             // Tn scores -> unnormalized attn
    float* sred   = sscore + Tn;          // 16 reduction scratch
    float* spart  = sred + 16;            // Dn weighted-sum partials
    float* scpart = spart + Dn;           // NTHREADS c-bias partials

    const int b   = blockIdx.x;
    const int tid = threadIdx.x;

    // ---- async load facts[b] into swizzled smem (16B cp.async) ----
    {
        const float4* fg = (const float4*)(facts + (size_t)b * (Tn * Dn));
        #pragma unroll
        for (int k = 0; k < (Tn * Dn / 4) / NTHREADS; ++k) {   // 25 iters
            int i  = tid + k * NTHREADS;
            int t  = i >> 5;        // 32 float4 groups per row
            int dg = i & 31;
            float4* dst = ((float4*)sf) + (t * 32 + (dg ^ (t & 31)));
            unsigned saddr = (unsigned)__cvta_generic_to_shared(dst);
            asm volatile("cp.async.cg.shared.global [%0], [%1], 16;\n"
                         :: "r"(saddr), "l"(fg + i) : "memory");
        }
        asm volatile("cp.async.commit_group;\n" ::: "memory");
    }

    if (tid < Dn) sq[tid]  = query[(size_t)b * Dn + tid];
    if (tid < Hn) sw2[tid] = W2[tid];
    __syncthreads();   // sq visible

    // ---- M[d][h] = (W1f - W1d)[d][h] + q[d] * W1m[d][h]  (tf32-rounded) ----
    #pragma unroll
    for (int k = 0; k < (Dn * Hn) / NTHREADS; ++k) {   // 8 iters
        int i = tid + k * NTHREADS;
        int d = i >> 4;
        int h = i & 15;
        float wf = W1[(128 + d) * Hn + h];
        float wd = W1[(256 + d) * Hn + h];
        float wm = W1[(384 + d) * Hn + h];
        uint32_t r = f2tf32((wf - wd) + sq[d] * wm);
        sM[i] = __uint_as_float(r);
    }

    // ---- c[h] = b1[h] + sum_d q[d]*(W1q + W1d)[d][h], parallel partials ----
    {
        int h     = tid & 15;
        int chunk = tid >> 4;   // 16 chunks x 8 d
        float acc = 0.f;
        #pragma unroll
        for (int j = 0; j < 8; ++j) {
            int d = chunk * 8 + j;
            acc += sq[d] * (W1[d * Hn + h] + W1[(256 + d) * Hn + h]);
        }
        scpart[tid] = acc;
    }
    __syncthreads();
    if (tid < Hn) {
        float acc = b1[tid];
        #pragma unroll
        for (int k = 0; k < 16; ++k) acc += scpart[k * 16 + tid];
        sc[tid] = acc;
    }
    asm volatile("cp.async.wait_group 0;\n" ::: "memory");
    __syncthreads();   // facts tile + sM + sc ready

    // ---- scores via tf32 MMA: S[200,16] = F[200,128] x M[128,16] ----
    {
        const int w    = tid >> 5;
        const int lane = tid & 31;
        const int gid  = lane >> 2;   // 0..7
        const int tig  = lane & 3;    // 0..3
        const float b2v = b2[0];

        // B fragments: M[k][h], k-major. 16 k-steps x 2 n-tiles x 2 regs = 64 regs.
        uint32_t Bf[16][2][2];
        #pragma unroll
        for (int ks = 0; ks < 16; ++ks) {
            #pragma unroll
            for (int nt = 0; nt < 2; ++nt) {
                Bf[ks][nt][0] = __float_as_uint(sM[(ks * 8 + tig)     * Hn + nt * 8 + gid]);
                Bf[ks][nt][1] = __float_as_uint(sM[(ks * 8 + tig + 4) * Hn + nt * 8 + gid]);
            }
        }

        // Warp w handles m-tiles w and w+8 (if < 13). 13 tiles cover t=0..207.
        #pragma unroll
        for (int pass = 0; pass < 2; ++pass) {
            int mt = w + pass * 8;
            if (mt >= 13) break;
            const int t0 = mt * 16 + gid;    // rows t0 and t0+8
            const int t1 = t0 + 8;
            const int sw0 = t0 & 31, sw1 = t1 & 31;
            const float* f0 = sf + t0 * Dn + tig;
            const float* f1 = sf + t1 * Dn + tig;

            float c0[4] = {0.f, 0.f, 0.f, 0.f};
            float c1[4] = {0.f, 0.f, 0.f, 0.f};
            #pragma unroll
            for (int ks = 0; ks < 16; ++ks) {
                uint32_t a[4];
                a[0] = f2tf32(f0[((2 * ks)     ^ sw0) << 2]);
                a[1] = f2tf32(f1[((2 * ks)     ^ sw1) << 2]);
                a[2] = f2tf32(f0[((2 * ks + 1) ^ sw0) << 2]);
                a[3] = f2tf32(f1[((2 * ks + 1) ^ sw1) << 2]);
                mma_tf32(c0, a, Bf[ks][0][0], Bf[ks][0][1]);
                mma_tf32(c1, a, Bf[ks][1][0], Bf[ks][1][1]);
            }

            // epilogue: score_t = b2 + sum_h sigmoid(preact+sc[h])*w2[h]
            // lane owns h = nt*8 + 2*tig, 2*tig+1 for rows t0 (c[0],c[1]) and t1 (c[2],c[3])
            float part0 = 0.f, part1 = 0.f;
            #pragma unroll
            for (int nt = 0; nt < 2; ++nt) {
                int h0 = nt * 8 + 2 * tig;
                float scA = sc[h0],  w2A = sw2[h0];
                float scB = sc[h0+1], w2B = sw2[h0+1];
                const float* cc = nt ? c1 : c0;
                part0 += w2A / (1.0f + __expf(-(cc[0] + scA)));
                part0 += w2B / (1.0f + __expf(-(cc[1] + scB)));
                part1 += w2A / (1.0f + __expf(-(cc[2] + scA)));
                part1 += w2B / (1.0f + __expf(-(cc[3] + scB)));
            }
            part0 += __shfl_xor_sync(0xffffffffu, part0, 1);
            part0 += __shfl_xor_sync(0xffffffffu, part0, 2);
            part1 += __shfl_xor_sync(0xffffffffu, part1, 1);
            part1 += __shfl_xor_sync(0xffffffffu, part1, 2);
            if (tig == 0) {
                if (t0 < Tn) {
                    float s = b2v + part0;
                    if (mask[(size_t)b * Tn + t0] == 0) s = NEGV;
                    sscore[t0] = s;
                }
                if (t1 < Tn) {
                    float s = b2v + part1;
                    if (mask[(size_t)b * Tn + t1] == 0) s = NEGV;
                    sscore[t1] = s;
                }
            }
        }
    }
    __syncthreads();

    // ---- softmax over T ----
    float v = (tid < Tn) ? sscore[tid] : -3.4e38f;
    #pragma unroll
    for (int o = 16; o > 0; o >>= 1) v = fmaxf(v, __shfl_xor_sync(0xffffffffu, v, o));
    if ((tid & 31) == 0) sred[tid >> 5] = v;
    __syncthreads();
    if (tid == 0) {
        float m = sred[0];
        #pragma unroll
        for (int w = 1; w < 8; ++w) m = fmaxf(m, sred[w]);
        sred[8] = m;
    }
    __syncthreads();
    float mx = sred[8];
    float e = 0.f;
    if (tid < Tn) {
        e = __expf(sscore[tid] - mx);
        sscore[tid] = e;     // unnormalized attn
    }
    #pragma unroll
    for (int o = 16; o > 0; o >>= 1) e += __shfl_xor_sync(0xffffffffu, e, o);
    if ((tid & 31) == 0) sred[tid >> 5] = e;
    __syncthreads();
    if (tid == 0) {
        float ssum = 0.f;
        #pragma unroll
        for (int w = 0; w < 8; ++w) ssum += sred[w];
        sred[9] = 1.0f / ssum;
    }
    __syncthreads();
    const float inv = sred[9];

    // ---- weighted sum: out[d] = inv * sum_t attn[t] * facts[t][d] ----
    {
        int d    = tid & 127;
        int half = tid >> 7;           // t-range split across the two half-blocks
        int dg   = d >> 2, dl = d & 3;
        float acc = 0.f;
        int t0 = half * 100;
        #pragma unroll 4
        for (int tt = 0; tt < 100; ++tt) {
            int t = t0 + tt;
            float f = sf[t * Dn + (((dg ^ (t & 31)) << 2) | dl)];
            acc += sscore[t] * f;
        }
        if (half) spart[d] = acc;
        __syncthreads();
        if (tid < Dn) out[(size_t)b * Dn + tid] = (acc + spart[tid]) * inv;
    }
}

extern "C" void kernel_launch(void* const* d_in, const int* in_sizes, int n_in,
                              void* d_out, int out_size) {
    const float* query = (const float*)d_in[0];
    const float* facts = (const float*)d_in[1];
    const int*   mask  = (const int*)d_in[2];
    const float* W1    = (const float*)d_in[3];
    const float* b1    = (const float*)d_in[4];
    const float* W2    = (const float*)d_in[5];
    const float* b2    = (const float*)d_in[6];
    float*       out   = (float*)d_out;

    int B = in_sizes[0] / Dn;   // 4096
    size_t smem = SMEM_FLOATS * sizeof(float);   // ~113.6 KB
    cudaFuncSetAttribute(din_kernel, cudaFuncAttributeMaxDynamicSharedMemorySize, (int)smem);
    din_kernel<<<B, NTHREADS, smem>>>(query, facts, mask, W1, b1, W2, b2, out);
}

// round 4
// speedup vs baseline: 1.4616x; 1.1071x over previous
#include <cuda_runtime.h>
#include <cstdint>
#include <cstddef>

#define Tn 200
#define Dn 128
#define Hn 16
#define NEGV (-4294967295.0f)
#define NTHREADS 512

// smem float counts: sf 25600 | sB 2048 (aliased by spart16) | sq 128 | sc 16 | sw2 16
//                    sscore 200 | sred 16 | scpart 256  => 28280 floats = 113.1 KB
#define SMEM_FLOATS (25600 + 2048 + 128 + 16 + 16 + 200 + 16 + 256)

__device__ __forceinline__ uint32_t f2tf32(float x) {
    uint32_t u;
    asm("cvt.rna.tf32.f32 %0, %1;" : "=r"(u) : "f"(x));
    return u;
}

__device__ __forceinline__ void mma_tf32(float c[4], const uint32_t a[4],
                                         uint32_t b0, uint32_t b1) {
    asm volatile(
        "mma.sync.aligned.m16n8k8.row.col.f32.tf32.tf32.f32 "
        "{%0,%1,%2,%3}, {%4,%5,%6,%7}, {%8,%9}, {%0,%1,%2,%3};"
        : "+f"(c[0]), "+f"(c[1]), "+f"(c[2]), "+f"(c[3])
        : "r"(a[0]), "r"(a[1]), "r"(a[2]), "r"(a[3]), "r"(b0), "r"(b1));
}

__global__ void __launch_bounds__(NTHREADS, 2) din_kernel(
    const float* __restrict__ query,
    const float* __restrict__ facts,
    const int* __restrict__ mask,
    const float* __restrict__ W1,
    const float* __restrict__ b1,
    const float* __restrict__ W2,
    const float* __restrict__ b2,
    float* __restrict__ out)
{
    extern __shared__ float smem[];
    float* sf     = smem;                 // swizzled facts tile (100 KB)
    float* sB     = sf + Tn*Dn;           // packed tf32 B fragments (2048 f); later: spart16
    float* sq     = sB + 2048;            // 128
    float* sc     = sq + Dn;              // 16
    float* sw2    = sc + Hn;              // 16
    float* sscore = sw2 + Hn;             // 200
    float* sred   = sscore + Tn;          // 16
    float* scpart = sred + 16;            // 256
    float* spart16 = sB;                  // alias: 16 x 128 weighted-sum partials

    const int b   = blockIdx.x;
    const int tid = threadIdx.x;

    // ---- stage A: rows 0..111 (3584 float4), stage B: rows 112..199 ----
    {
        const float4* fg = (const float4*)(facts + (size_t)b * (Tn * Dn));
        #pragma unroll
        for (int k = 0; k < 7; ++k) {
            int i  = tid + k * NTHREADS;          // < 3584
            int t  = i >> 5;
            int dg = i & 31;
            float4* dst = ((float4*)sf) + (t * 32 + (dg ^ (t & 31)));
            unsigned saddr = (unsigned)__cvta_generic_to_shared(dst);
            asm volatile("cp.async.cg.shared.global [%0], [%1], 16;\n"
                         :: "r"(saddr), "l"(fg + i) : "memory");
        }
        asm volatile("cp.async.commit_group;\n" ::: "memory");
        #pragma unroll
        for (int k = 0; k < 6; ++k) {
            int i = 3584 + tid + k * NTHREADS;
            if (i < 6400) {
                int t  = i >> 5;
                int dg = i & 31;
                float4* dst = ((float4*)sf) + (t * 32 + (dg ^ (t & 31)));
                unsigned saddr = (unsigned)__cvta_generic_to_shared(dst);
                asm volatile("cp.async.cg.shared.global [%0], [%1], 16;\n"
                             :: "r"(saddr), "l"(fg + i) : "memory");
            }
        }
        asm volatile("cp.async.commit_group;\n" ::: "memory");
    }

    if (tid < Dn) sq[tid]  = query[(size_t)b * Dn + tid];
    if (tid >= Dn && tid < Dn + Hn) sw2[tid - Dn] = W2[tid - Dn];
    __syncthreads();   // sq visible

    // ---- folded weights, packed for conflict-free LDS.64 B-fragment reads:
    // sB[(((ks*2+nt)*8+gid)*4+tig)*2 + j] = tf32(M[8ks+tig+4j][nt*8+gid])
    #pragma unroll
    for (int k = 0; k < (Dn * Hn) / NTHREADS; ++k) {   // 4 iters
        int i = tid + k * NTHREADS;
        int d = i >> 4;
        int h = i & 15;
        float wf = W1[(128 + d) * Hn + h];
        float wd = W1[(256 + d) * Hn + h];
        float wm = W1[(384 + d) * Hn + h];
        uint32_t r = f2tf32((wf - wd) + sq[d] * wm);
        int ks = d >> 3, tig = d & 3, j = (d >> 2) & 1;
        int nt = h >> 3, gid = h & 7;
        sB[(((ks * 2 + nt) * 8 + gid) * 4 + tig) * 2 + j] = __uint_as_float(r);
    }

    // ---- c[h] = b1[h] + sum_d q[d]*(W1q + W1d)[d][h] ----
    if (tid < 256) {
        int h     = tid & 15;
        int chunk = tid >> 4;   // 16 chunks x 8 d
        float acc = 0.f;
        #pragma unroll
        for (int j = 0; j < 8; ++j) {
            int d = chunk * 8 + j;
            acc += sq[d] * (W1[d * Hn + h] + W1[(256 + d) * Hn + h]);
        }
        scpart[tid] = acc;
    }
    __syncthreads();
    if (tid < Hn) {
        float acc = b1[tid];
        #pragma unroll
        for (int k = 0; k < 16; ++k) acc += scpart[k * 16 + tid];
        sc[tid] = acc;
    }

    const int w    = tid >> 5;
    const int lane = tid & 31;
    const int gid  = lane >> 2;   // 0..7
    const int tig  = lane & 3;    // 0..3

    // ---- scores via tf32 MMA, warp w -> m-tile w, two load stages ----
    #pragma unroll
    for (int stage = 0; stage < 2; ++stage) {
        if (stage == 0)
            asm volatile("cp.async.wait_group 1;\n" ::: "memory");
        else
            asm volatile("cp.async.wait_group 0;\n" ::: "memory");
        __syncthreads();

        const int mt = w;
        bool active = (stage == 0) ? (mt < 7) : (mt >= 7 && mt < 13);
        if (active) {
            const int t0 = mt * 16 + gid;
            const int t1 = t0 + 8;
            const int sw0 = t0 & 31, sw1 = t1 & 31;
            const float* f0 = sf + t0 * Dn + tig;
            const float* f1 = sf + t1 * Dn + tig;
            const float2* Bp = (const float2*)sB;

            float c0[4] = {0.f, 0.f, 0.f, 0.f};
            float c1[4] = {0.f, 0.f, 0.f, 0.f};
            #pragma unroll 8
            for (int ks = 0; ks < 16; ++ks) {
                uint32_t a[4];
                a[0] = f2tf32(f0[((2 * ks)     ^ sw0) << 2]);
                a[1] = f2tf32(f1[((2 * ks)     ^ sw1) << 2]);
                a[2] = f2tf32(f0[((2 * ks + 1) ^ sw0) << 2]);
                a[3] = f2tf32(f1[((2 * ks + 1) ^ sw1) << 2]);
                float2 bA = Bp[((ks * 2 + 0) * 8 + gid) * 4 + tig];
                float2 bB = Bp[((ks * 2 + 1) * 8 + gid) * 4 + tig];
                mma_tf32(c0, a, __float_as_uint(bA.x), __float_as_uint(bA.y));
                mma_tf32(c1, a, __float_as_uint(bB.x), __float_as_uint(bB.y));
            }

            float part0 = 0.f, part1 = 0.f;
            #pragma unroll
            for (int nt = 0; nt < 2; ++nt) {
                int h0 = nt * 8 + 2 * tig;
                float scA = sc[h0],   w2A = sw2[h0];
                float scB = sc[h0+1], w2B = sw2[h0+1];
                const float* cc = nt ? c1 : c0;
                part0 += w2A / (1.0f + __expf(-(cc[0] + scA)));
                part0 += w2B / (1.0f + __expf(-(cc[1] + scB)));
                part1 += w2A / (1.0f + __expf(-(cc[2] + scA)));
                part1 += w2B / (1.0f + __expf(-(cc[3] + scB)));
            }
            part0 += __shfl_xor_sync(0xffffffffu, part0, 1);
            part0 += __shfl_xor_sync(0xffffffffu, part0, 2);
            part1 += __shfl_xor_sync(0xffffffffu, part1, 1);
            part1 += __shfl_xor_sync(0xffffffffu, part1, 2);
            if (tig == 0) {
                float b2v = b2[0];
                if (t0 < Tn) {
                    float s = b2v + part0;
                    if (mask[(size_t)b * Tn + t0] == 0) s = NEGV;
                    sscore[t0] = s;
                }
                if (t1 < Tn) {
                    float s = b2v + part1;
                    if (mask[(size_t)b * Tn + t1] == 0) s = NEGV;
                    sscore[t1] = s;
                }
            }
        }
    }
    __syncthreads();

    // ---- softmax over T ----
    float v = (tid < Tn) ? sscore[tid] : -3.4e38f;
    #pragma unroll
    for (int o = 16; o > 0; o >>= 1) v = fmaxf(v, __shfl_xor_sync(0xffffffffu, v, o));
    if (lane == 0) sred[w] = v;
    __syncthreads();
    if (tid == 0) {
        float m = sred[0];
        #pragma unroll
        for (int k = 1; k < 7; ++k) m = fmaxf(m, sred[k]);
        sred[14] = m;
    }
    __syncthreads();
    float mx = sred[14];
    float e = 0.f;
    if (tid < Tn) {
        e = __expf(sscore[tid] - mx);
        sscore[tid] = e;     // unnormalized attn
    }
    #pragma unroll
    for (int o = 16; o > 0; o >>= 1) e += __shfl_xor_sync(0xffffffffu, e, o);
    if (lane == 0) sred[w] = e;
    __syncthreads();
    if (tid == 0) {
        float ssum = 0.f;
        #pragma unroll
        for (int k = 0; k < 7; ++k) ssum += sred[k];
        sred[15] = 1.0f / ssum;
    }
    __syncthreads();   // also: sB is dead from here; spart16 aliases it
    const float inv = sred[15];

    // ---- weighted sum: thread (slice=w, dg=lane), LDS.128, t = slice + 16*i ----
    {
        const int dg = lane;
        float4 acc = make_float4(0.f, 0.f, 0.f, 0.f);
        // swizzled group index alternates between dg^s and dg^(s+16) as t steps by 16
        const float4* base = (const float4*)sf;
        int t = w;
        #pragma unroll 4
        for (; t < Tn; t += 16) {
            float a0 = sscore[t];
            float4 f4 = base[t * 32 + (dg ^ (t & 31))];
            acc.x += a0 * f4.x; acc.y += a0 * f4.y;
            acc.z += a0 * f4.z; acc.w += a0 * f4.w;
        }
        ((float4*)spart16)[w * 32 + dg] = acc;
    }
    __syncthreads();
    if (tid < Dn) {
        float acc = 0.f;
        #pragma unroll
        for (int s = 0; s < 16; ++s) acc += spart16[s * Dn + tid];
        out[(size_t)b * Dn + tid] = acc * inv;
    }
}

extern "C" void kernel_launch(void* const* d_in, const int* in_sizes, int n_in,
                              void* d_out, int out_size) {
    const float* query = (const float*)d_in[0];
    const float* facts = (const float*)d_in[1];
    const int*   mask  = (const int*)d_in[2];
    const float* W1    = (const float*)d_in[3];
    const float* b1    = (const float*)d_in[4];
    const float* W2    = (const float*)d_in[5];
    const float* b2    = (const float*)d_in[6];
    float*       out   = (float*)d_out;

    int B = in_sizes[0] / Dn;   // 4096
    size_t smem = SMEM_FLOATS * sizeof(float);   // ~113.1 KB
    cudaFuncSetAttribute(din_kernel, cudaFuncAttributeMaxDynamicSharedMemorySize, (int)smem);
    din_kernel<<<B, NTHREADS, smem>>>(query, facts, mask, W1, b1, W2, b2, out);
}

// round 5
// speedup vs baseline: 1.8878x; 1.2916x over previous
#include <cuda_runtime.h>
#include <cstdint>
#include <cstddef>

#define Tn 200
#define Dn 128
#define Hn 16
#define NEGV (-4294967295.0f)
#define NTHREADS 512

// smem float counts: sf 25600 | sB 2048 (aliased by spart16) | sq 128 | sc 16 | sw2 16
//                    sscore 200 | sred 16 | scpart 256  => 28280 floats = 113.1 KB
#define SMEM_FLOATS (25600 + 2048 + 128 + 16 + 16 + 200 + 16 + 256)

__device__ __forceinline__ uint32_t f2tf32(float x) {
    uint32_t u;
    asm("cvt.rna.tf32.f32 %0, %1;" : "=r"(u) : "f"(x));
    return u;
}

__device__ __forceinline__ void mma_tf32(float c[4], const uint32_t a[4],
                                         uint32_t b0, uint32_t b1) {
    asm volatile(
        "mma.sync.aligned.m16n8k8.row.col.f32.tf32.tf32.f32 "
        "{%0,%1,%2,%3}, {%4,%5,%6,%7}, {%8,%9}, {%0,%1,%2,%3};"
        : "+f"(c[0]), "+f"(c[1]), "+f"(c[2]), "+f"(c[3])
        : "r"(a[0]), "r"(a[1]), "r"(a[2]), "r"(a[3]), "r"(b0), "r"(b1));
}

__global__ void __launch_bounds__(NTHREADS, 2) din_kernel(
    const float* __restrict__ query,
    const float* __restrict__ facts,
    const int* __restrict__ mask,
    const float* __restrict__ W1,
    const float* __restrict__ b1,
    const float* __restrict__ W2,
    const float* __restrict__ b2,
    float* __restrict__ out)
{
    extern __shared__ float smem[];
    float* sf     = smem;                 // swizzled facts tile (100 KB)
    float* sB     = sf + Tn*Dn;           // packed tf32 B fragments (2048 f); later: spart16
    float* sq     = sB + 2048;            // 128
    float* sc     = sq + Dn;              // 16
    float* sw2    = sc + Hn;              // 16
    float* sscore = sw2 + Hn;             // 200 (unnormalized attn = exp(score))
    float* sred   = sscore + Tn;          // 16
    float* scpart = sred + 16;            // 256
    float* spart16 = sB;                  // alias: 16 x 128 weighted-sum partials

    const int b   = blockIdx.x;
    const int tid = threadIdx.x;
    const float b2v = b2[0];

    // ---- stage A: rows 0..111 (3584 float4), stage B: rows 112..199 ----
    {
        const float4* fg = (const float4*)(facts + (size_t)b * (Tn * Dn));
        #pragma unroll
        for (int k = 0; k < 7; ++k) {
            int i  = tid + k * NTHREADS;          // < 3584
            int t  = i >> 5;
            int dg = i & 31;
            float4* dst = ((float4*)sf) + (t * 32 + (dg ^ (t & 31)));
            unsigned saddr = (unsigned)__cvta_generic_to_shared(dst);
            asm volatile("cp.async.cg.shared.global [%0], [%1], 16;\n"
                         :: "r"(saddr), "l"(fg + i) : "memory");
        }
        asm volatile("cp.async.commit_group;\n" ::: "memory");
        #pragma unroll
        for (int k = 0; k < 6; ++k) {
            int i = 3584 + tid + k * NTHREADS;
            if (i < 6400) {
                int t  = i >> 5;
                int dg = i & 31;
                float4* dst = ((float4*)sf) + (t * 32 + (dg ^ (t & 31)));
                unsigned saddr = (unsigned)__cvta_generic_to_shared(dst);
                asm volatile("cp.async.cg.shared.global [%0], [%1], 16;\n"
                             :: "r"(saddr), "l"(fg + i) : "memory");
            }
        }
        asm volatile("cp.async.commit_group;\n" ::: "memory");
    }

    if (tid < Dn) sq[tid]  = query[(size_t)b * Dn + tid];
    if (tid >= Dn && tid < Dn + Hn) sw2[tid - Dn] = W2[tid - Dn];
    __syncthreads();   // sq visible

    // ---- folded weights, packed so each ks is ONE LDS.128:
    // sB[((ks*8+gid)*4+tig)*4 + (nt*2+j)] = tf32(M[8ks+tig+4j][nt*8+gid])
    #pragma unroll
    for (int k = 0; k < (Dn * Hn) / NTHREADS; ++k) {   // 4 iters
        int i = tid + k * NTHREADS;
        int d = i >> 4;
        int h = i & 15;
        float wf = W1[(128 + d) * Hn + h];
        float wd = W1[(256 + d) * Hn + h];
        float wm = W1[(384 + d) * Hn + h];
        uint32_t r = f2tf32((wf - wd) + sq[d] * wm);
        int ks = d >> 3, tig = d & 3, j = (d >> 2) & 1;
        int nt = h >> 3, gid = h & 7;
        sB[(((ks * 8 + gid) * 4 + tig) * 4) + nt * 2 + j] = __uint_as_float(r);
    }

    // ---- c[h] = b1[h] + sum_d q[d]*(W1q + W1d)[d][h] ----
    if (tid < 256) {
        int h     = tid & 15;
        int chunk = tid >> 4;   // 16 chunks x 8 d
        float acc = 0.f;
        #pragma unroll
        for (int j = 0; j < 8; ++j) {
            int d = chunk * 8 + j;
            acc += sq[d] * (W1[d * Hn + h] + W1[(256 + d) * Hn + h]);
        }
        scpart[tid] = acc;
    }
    __syncthreads();
    if (tid < Hn) {
        float acc = b1[tid];
        #pragma unroll
        for (int k = 0; k < 16; ++k) acc += scpart[k * 16 + tid];
        sc[tid] = acc;
    }

    const int w    = tid >> 5;
    const int lane = tid & 31;
    const int gid  = lane >> 2;   // 0..7
    const int tig  = lane & 3;    // 0..3

    // ---- scores via tf32 MMA (raw fp32 bits; HW truncates), warp w -> m-tile w ----
    #pragma unroll
    for (int stage = 0; stage < 2; ++stage) {
        if (stage == 0)
            asm volatile("cp.async.wait_group 1;\n" ::: "memory");
        else
            asm volatile("cp.async.wait_group 0;\n" ::: "memory");
        __syncthreads();

        const int mt = w;
        bool active = (stage == 0) ? (mt < 7) : (mt >= 7 && mt < 13);
        if (active) {
            const int t0 = mt * 16 + gid;
            const int t1 = t0 + 8;
            const int sw0 = t0 & 31, sw1 = t1 & 31;
            const float* f0 = sf + t0 * Dn + tig;
            const float* f1 = sf + t1 * Dn + tig;
            const float4* Bp = ((const float4*)sB) + gid * 4 + tig;

            // prefetch mask (overlaps MMA loop)
            int m0 = mask[(size_t)b * Tn + t0];
            int m1 = (t1 < Tn) ? mask[(size_t)b * Tn + t1] : 0;

            float c0[4] = {0.f, 0.f, 0.f, 0.f};
            float c1[4] = {0.f, 0.f, 0.f, 0.f};
            #pragma unroll
            for (int ks = 0; ks < 16; ++ks) {
                uint32_t a[4];
                a[0] = __float_as_uint(f0[((2 * ks)     ^ sw0) << 2]);
                a[1] = __float_as_uint(f1[((2 * ks)     ^ sw1) << 2]);
                a[2] = __float_as_uint(f0[((2 * ks + 1) ^ sw0) << 2]);
                a[3] = __float_as_uint(f1[((2 * ks + 1) ^ sw1) << 2]);
                float4 bf = Bp[ks * 32];
                mma_tf32(c0, a, __float_as_uint(bf.x), __float_as_uint(bf.y));
                mma_tf32(c1, a, __float_as_uint(bf.z), __float_as_uint(bf.w));
            }

            // epilogue: score -> exp(score) directly (no max pass; exp(NEG)=0)
            float part0 = 0.f, part1 = 0.f;
            #pragma unroll
            for (int nt = 0; nt < 2; ++nt) {
                int h0 = nt * 8 + 2 * tig;
                float scA = sc[h0],   w2A = sw2[h0];
                float scB = sc[h0+1], w2B = sw2[h0+1];
                const float* cc = nt ? c1 : c0;
                part0 += __fdividef(w2A, 1.0f + __expf(-(cc[0] + scA)));
                part0 += __fdividef(w2B, 1.0f + __expf(-(cc[1] + scB)));
                part1 += __fdividef(w2A, 1.0f + __expf(-(cc[2] + scA)));
                part1 += __fdividef(w2B, 1.0f + __expf(-(cc[3] + scB)));
            }
            part0 += __shfl_xor_sync(0xffffffffu, part0, 1);
            part0 += __shfl_xor_sync(0xffffffffu, part0, 2);
            part1 += __shfl_xor_sync(0xffffffffu, part1, 1);
            part1 += __shfl_xor_sync(0xffffffffu, part1, 2);

            float e0 = m0 ? __expf(b2v + part0) : 0.f;               // t0 always < Tn
            float e1 = (t1 < Tn && m1) ? __expf(b2v + part1) : 0.f;
            if (tig == 0) {
                sscore[t0] = e0;
                if (t1 < Tn) sscore[t1] = e1;
            }
            // warp-level sum of exp over this tile's 16 rows (quad-uniform values)
            float es = e0 + e1;
            es += __shfl_xor_sync(0xffffffffu, es, 4);
            es += __shfl_xor_sync(0xffffffffu, es, 8);
            es += __shfl_xor_sync(0xffffffffu, es, 16);
            if (lane == 0) sred[w] = es;
        }
    }
    __syncthreads();   // sscore + sred[0..12] ready; sB dead (spart16 aliases)

    if (tid == 0) {
        float ssum = 0.f;
        #pragma unroll
        for (int k = 0; k < 13; ++k) ssum += sred[k];
        sred[15] = 1.0f / ssum;
    }

    // ---- weighted sum: slice w handles t = w + 16*i, dual-pointer streams ----
    {
        const int dg = lane;
        const float4* p0 = ((const float4*)sf) + w * 32 + (dg ^ w);                 // t = w + 32i
        const float4* p1 = ((const float4*)sf) + (w + 16) * 32 + (dg ^ (w + 16));   // t = w+16+32i
        float4 acc = make_float4(0.f, 0.f, 0.f, 0.f);
        #pragma unroll
        for (int i = 0; i < 6; ++i) {
            float a0 = sscore[w + 32 * i];
            float4 f4 = p0[i * 1024];
            acc.x += a0 * f4.x; acc.y += a0 * f4.y; acc.z += a0 * f4.z; acc.w += a0 * f4.w;
            float a1 = sscore[w + 16 + 32 * i];
            float4 g4 = p1[i * 1024];
            acc.x += a1 * g4.x; acc.y += a1 * g4.y; acc.z += a1 * g4.z; acc.w += a1 * g4.w;
        }
        if (w < 8) {   // 13th element of stream0: t = w + 192
            float a0 = sscore[w + 192];
            float4 f4 = p0[6 * 1024];
            acc.x += a0 * f4.x; acc.y += a0 * f4.y; acc.z += a0 * f4.z; acc.w += a0 * f4.w;
        }
        ((float4*)spart16)[w * 32 + dg] = acc;
    }
    __syncthreads();
    if (tid < Dn) {
        const float inv = sred[15];
        float acc = 0.f;
        #pragma unroll
        for (int s = 0; s < 16; ++s) acc += spart16[s * Dn + tid];
        out[(size_t)b * Dn + tid] = acc * inv;
    }
}

extern "C" void kernel_launch(void* const* d_in, const int* in_sizes, int n_in,
                              void* d_out, int out_size) {
    const float* query = (const float*)d_in[0];
    const float* facts = (const float*)d_in[1];
    const int*   mask  = (const int*)d_in[2];
    const float* W1    = (const float*)d_in[3];
    const float* b1    = (const float*)d_in[4];
    const float* W2    = (const float*)d_in[5];
    const float* b2    = (const float*)d_in[6];
    float*       out   = (float*)d_out;

    int B = in_sizes[0] / Dn;   // 4096
    size_t smem = SMEM_FLOATS * sizeof(float);   // ~113.1 KB
    cudaFuncSetAttribute(din_kernel, cudaFuncAttributeMaxDynamicSharedMemorySize, (int)smem);
    din_kernel<<<B, NTHREADS, smem>>>(query, facts, mask, W1, b1, W2, b2, out);
}